// round 14
// baseline (speedup 1.0000x reference)
#include <cuda_runtime.h>
#include <cuda_bf16.h>
#include <cstdint>
#include <cstddef>

#define SEQ   512
#define BATCH 64
#define HS    1024
#define NG    4096
#define MROWS (SEQ*BATCH)     // 32768
#define NB_PERS 128
#define GP 36                 // padded gate-smem row stride (floats)
#define HB (BATCH*2*HS)       // one h buffer (hi|lo), elements
#define NCHUNK 32             // inproj k-chunks of 32
#define SMEM_INPROJ (3*32768 + 1024)
// layer: V 131072 | A 3x16384 | gA 9216 | gB 9216 | align 1024
#define SMEM_LAYER (1024 + 131072 + 49152 + 9216 + 9216)

typedef unsigned long long u64;
typedef __nv_bfloat16 bf16;

// ---------------- static device scratch ----------------
__device__ float g_pre[(size_t)MROWS * NG];          // gate pre-activations (permuted cols)
__device__ bf16  g_xs[(size_t)MROWS * 2 * HS];       // input splits (hi|lo); layer0 h splits
__device__ bf16  g_hs[2 * HB];                       // double-buffered h splits
__device__ bf16  g_Us0[(size_t)NG * 2 * HS];         // permuted weight splits
__device__ bf16  g_Vs0[(size_t)NG * 2 * HS];
__device__ bf16  g_Us1[(size_t)NG * 2 * HS];
__device__ bf16  g_Vs1[(size_t)NG * 2 * HS];

// ---------------- distributed-flag grid barrier ----------------
// Arrival: one release-store per CTA to its OWN flag (no same-address atomic
// serialization — R13's single-counter atomic cost ~128*27 cyc/step).
// Wait: threads 0..127 each poll one flag (acquire), then __syncthreads.
// Flags are monotonic generation counters, never reset -> graph-replay safe.
__device__ unsigned g_arr[NB_PERS];

__device__ __forceinline__ void grid_barrier(unsigned& gen) {
    gen += 1;
    __syncthreads();   // all prior smem/global work of this CTA done
    if (threadIdx.x == 0)
        asm volatile("st.release.gpu.u32 [%0], %1;"
                     :: "l"(&g_arr[blockIdx.x]), "r"(gen) : "memory");
    if (threadIdx.x < NB_PERS) {
        unsigned v;
        while (true) {
            asm volatile("ld.acquire.gpu.u32 %0, [%1];"
                         : "=r"(v) : "l"(&g_arr[threadIdx.x]) : "memory");
            if ((int)(v - gen) >= 0) break;
            __nanosleep(20);
        }
    }
    __syncthreads();
}

// ---------------- mma.sync building blocks (validated R4-R13) ----------------
__device__ __forceinline__ uint32_t smem_u32(const void* p) {
    uint32_t a;
    asm("{ .reg .u64 t; cvta.to.shared.u64 t, %1; cvt.u32.u64 %0, t; }" : "=r"(a) : "l"(p));
    return a;
}
__device__ __forceinline__ void ldsm4(uint32_t* f, uint32_t addr) {
    asm volatile("ldmatrix.sync.aligned.m8n8.x4.shared.b16 {%0,%1,%2,%3}, [%4];"
        : "=r"(f[0]), "=r"(f[1]), "=r"(f[2]), "=r"(f[3]) : "r"(addr));
}
__device__ __forceinline__ void mma16816(float* d, const uint32_t* a, uint32_t b0, uint32_t b1) {
    asm volatile("mma.sync.aligned.m16n8k16.row.col.f32.bf16.bf16.f32 "
        "{%0,%1,%2,%3}, {%4,%5,%6,%7}, {%8,%9}, {%0,%1,%2,%3};"
        : "+f"(d[0]), "+f"(d[1]), "+f"(d[2]), "+f"(d[3])
        : "r"(a[0]), "r"(a[1]), "r"(a[2]), "r"(a[3]), "r"(b0), "r"(b1));
}
__device__ __forceinline__ uint32_t swz(uint32_t r, uint32_t c16) {
    return r * 128u + ((c16 ^ (r & 7u)) << 4);
}
__device__ __forceinline__ uint32_t a_addr(uint32_t base, int lane, int m0, int k0) {
    int sel = lane >> 3;
    uint32_t row = (uint32_t)(m0 + (lane & 7) + ((sel & 1) << 3));
    uint32_t c16 = (uint32_t)((k0 >> 3) + (sel >> 1));
    return base + swz(row, c16);
}
__device__ __forceinline__ uint32_t b_addr(uint32_t base, int lane, int n0, int k0) {
    int sel = lane >> 3;
    uint32_t row = (uint32_t)(n0 + (lane & 7) + ((sel >> 1) << 3));
    uint32_t c16 = (uint32_t)((k0 >> 3) + (sel & 1));
    return base + swz(row, c16);
}
__device__ __forceinline__ void cp16(uint32_t dst, const void* src) {
    asm volatile("cp.async.cg.shared.global [%0], [%1], 16;" :: "r"(dst), "l"(src));
}

// sync-path tile load into swizzled smem ([rows x 64] bf16, row stride ld)
__device__ __forceinline__ void load_tile(uint32_t sdst, const bf16* __restrict__ src,
                                          int rows, int ld) {
    const int chunks = rows * 8;
    for (int i = threadIdx.x; i < chunks; i += 256) {
        int r = i >> 3, c = i & 7;
        const uint4* p = reinterpret_cast<const uint4*>(src + (size_t)r * ld + c * 8);
        uint4 v = __ldg(p);
        asm volatile("st.shared.v4.b32 [%0], {%1,%2,%3,%4};"
                     :: "r"(sdst + swz((uint32_t)r, (uint32_t)c)),
                        "r"(v.x), "r"(v.y), "r"(v.z), "r"(v.w));
    }
}
// async stage of a combined [128 x 64] tile: cols 0-31 = hi k-chunk, 32-63 = lo.
__device__ __forceinline__ void stage_tile_hilo(uint32_t sdst, const bf16* __restrict__ src) {
    const int tid = threadIdx.x;
#pragma unroll
    for (int q = 0; q < 4; q++) {
        int i = tid + q * 256;
        int r = i >> 3, c = i & 7;
        const bf16* s = src + (size_t)r * 2048 + (c < 4 ? c * 8 : 1024 + (c - 4) * 8);
        cp16(sdst + swz((uint32_t)r, (uint32_t)c), s);
    }
}
// async stage: A pair (64 rows x 64 cols, hi tile + lo tile of 8KB each)
__device__ __forceinline__ void stage_A(uint32_t sdst, const bf16* __restrict__ src) {
    const int tid = threadIdx.x;
#pragma unroll
    for (int s = 0; s < 2; s++) {
#pragma unroll
        for (int q = 0; q < 2; q++) {
            int i = tid + q * 256;
            int r = i >> 3, c = i & 7;
            cp16(sdst + (uint32_t)s * 8192u + swz((uint32_t)r, (uint32_t)c),
                 src + s * 1024 + (size_t)r * 2048 + c * 8);
        }
    }
}

// ---------------- activations ----------------
__device__ __forceinline__ float sigmoid_acc(float x) {
    return 1.0f / (1.0f + __expf(-x));
}
__device__ __forceinline__ float tanh_acc(float x) {
    float e = __expf(-2.0f * fabsf(x));
    float t = (1.0f - e) / (1.0f + e);
    return copysignf(t, x);
}
__device__ __forceinline__ void split2(float v, bf16& hi, bf16& lo) {
    hi = __float2bfloat16(v);
    lo = __float2bfloat16(v - __bfloat162float(hi));
}

// =================================================================================
// split kernels. Weight rows gate-permuted: orig row r = g*1024+u -> 4u+g.
// =================================================================================
__global__ __launch_bounds__(256) void k_split_x(const float* __restrict__ x) {
    size_t i = (size_t)blockIdx.x * 256 + threadIdx.x;
    size_t m = i >> 10, k = i & 1023;
    bf16 hi, lo; split2(x[i], hi, lo);
    g_xs[m * 2048 + k]        = hi;
    g_xs[m * 2048 + 1024 + k] = lo;
}
__global__ __launch_bounds__(256) void k_split_w4(
    const float* __restrict__ W0, const float* __restrict__ W1,
    const float* __restrict__ W2, const float* __restrict__ W3,
    bf16* __restrict__ d0, bf16* __restrict__ d1,
    bf16* __restrict__ d2, bf16* __restrict__ d3)
{
    const float* W; bf16* dst;
    switch (blockIdx.y) {
        case 0:  W = W0; dst = d0; break;
        case 1:  W = W1; dst = d1; break;
        case 2:  W = W2; dst = d2; break;
        default: W = W3; dst = d3; break;
    }
    size_t i = (size_t)blockIdx.x * 256 + threadIdx.x;
    size_t n = i >> 10, k = i & 1023;
    size_t gidx = n >> 10, u = n & 1023;
    size_t np = u * 4 + gidx;
    bf16 hi, lo; split2(W[i], hi, lo);
    dst[np * 2048 + k]        = hi;
    dst[np * 2048 + 1024 + k] = lo;
}

// =================================================================================
// Input projection — unchanged R7/R12 config (measured 74.9% tensor = near ceiling).
// =================================================================================
__global__ __launch_bounds__(256, 2) void k_inproj_t(
    const bf16* __restrict__ A, const bf16* __restrict__ W,
    float* __restrict__ C)
{
    extern __shared__ char dsm[];
    const uint32_t sbase = (smem_u32(dsm) + 1023u) & ~1023u;
    const int tid = threadIdx.x, wid = tid >> 5, lane = tid & 31;
    const int m0 = blockIdx.y * 128, n0 = blockIdx.x * 128;
    const int mi = wid & 3, ni = wid >> 2;

    const bf16* Arow = A + (size_t)m0 * 2048;
    const bf16* Wrow = W + (size_t)n0 * 2048;

    auto issue_stage = [&](int kb) {
        const uint32_t st = sbase + (uint32_t)(kb % 3) * 32768u;
        stage_tile_hilo(st,          Arow + kb * 32);
        stage_tile_hilo(st + 16384u, Wrow + kb * 32);
        asm volatile("cp.async.commit_group;");
    };

    float acc[2][8][4];
#pragma unroll
    for (int a = 0; a < 2; a++)
#pragma unroll
        for (int b = 0; b < 8; b++)
#pragma unroll
            for (int cpos = 0; cpos < 4; cpos++) acc[a][b][cpos] = 0.f;

    issue_stage(0);
    issue_stage(1);

#pragma unroll 1
    for (int kb = 0; kb < NCHUNK; kb++) {
        if (kb == NCHUNK - 1) asm volatile("cp.async.wait_group 0;");
        else                  asm volatile("cp.async.wait_group 1;");
        __syncthreads();
        if (kb + 2 < NCHUNK) issue_stage(kb + 2);

        const uint32_t st = sbase + (uint32_t)(kb % 3) * 32768u;
        const uint32_t sA = st, sB = st + 16384u;
#pragma unroll
        for (int ks = 0; ks < 2; ks++) {
            const int k0 = ks * 16;
            uint32_t ah[2][4], al[2][4];
#pragma unroll
            for (int mf = 0; mf < 2; mf++) {
                ldsm4(ah[mf], a_addr(sA, lane, mi * 32 + mf * 16, k0));
                ldsm4(al[mf], a_addr(sA, lane, mi * 32 + mf * 16, k0 + 32));
            }
#pragma unroll
            for (int np = 0; np < 4; np++) {
                const int nt = ni * 64 + np * 16;
                uint32_t bh[4], bl[4];
                ldsm4(bh, b_addr(sB, lane, nt, k0));
#pragma unroll
                for (int mf = 0; mf < 2; mf++) {
                    mma16816(acc[mf][np * 2],     ah[mf], bh[0], bh[1]);
                    mma16816(acc[mf][np * 2 + 1], ah[mf], bh[2], bh[3]);
                    mma16816(acc[mf][np * 2],     al[mf], bh[0], bh[1]);
                    mma16816(acc[mf][np * 2 + 1], al[mf], bh[2], bh[3]);
                }
                ldsm4(bl, b_addr(sB, lane, nt, k0 + 32));
#pragma unroll
                for (int mf = 0; mf < 2; mf++) {
                    mma16816(acc[mf][np * 2],     ah[mf], bl[0], bl[1]);
                    mma16816(acc[mf][np * 2 + 1], ah[mf], bl[2], bl[3]);
                }
            }
        }
    }

    const int r = lane >> 2, cq = (lane & 3) * 2;
#pragma unroll
    for (int mf = 0; mf < 2; mf++) {
#pragma unroll
        for (int nf = 0; nf < 8; nf++) {
            const int ncol = n0 + ni * 64 + nf * 8 + cq;
            const int row0 = m0 + mi * 32 + mf * 16 + r;
            *reinterpret_cast<float2*>(C + (size_t)row0 * NG + ncol) =
                make_float2(acc[mf][nf][0], acc[mf][nf][1]);
            *reinterpret_cast<float2*>(C + (size_t)(row0 + 8) * NG + ncol) =
                make_float2(acc[mf][nf][2], acc[mf][nf][3]);
        }
    }
}

// =================================================================================
// Persistent LSTM layer, CLUSTERED K-SPLIT (R13 winner) + flag barrier + pre prefetch.
// 64 clusters x 2 CTAs. CTA (cid, rank): gate cols [64cid,+64), K-half [512rank,+512).
// =================================================================================
__global__ __launch_bounds__(256) __cluster_dims__(2, 1, 1)
void k_layer_c(
    const bf16* __restrict__ Vs, const float* __restrict__ pre,
    const float* __restrict__ b1, const float* __restrict__ b2,
    float* __restrict__ outbuf, bf16* __restrict__ xsplit,
    float* __restrict__ dh, float* __restrict__ dc)
{
    extern __shared__ char dsm[];
    const uint32_t sbase = (smem_u32(dsm) + 1023u) & ~1023u;
    const uint32_t sV  = sbase;               // 16 tiles x 8192 (hi 0..7, lo 8..15)
    const uint32_t sA  = sbase + 131072u;     // 3 stages x 16384
    const uint32_t sGA = sbase + 180224u;     // own partial   [64][GP] fp32
    const uint32_t sGB = sbase + 189440u;     // partner partial [64][GP] fp32
    const int tid = threadIdx.x, wid = tid >> 5, lane = tid & 31;
    const int bx = blockIdx.x;
    const int cid = bx >> 1;
    uint32_t rank;
    asm("mov.u32 %0, %%cluster_ctarank;" : "=r"(rank));
    const int mi = wid & 3, ni = wid >> 2;
    const int b  = tid >> 2;
    const int ul = (tid & 3) * 2;
    const int u0g  = cid * 16 + (int)rank * 8 + ul;
    const int col0 = 4 * u0g;
    const int kbase = (int)rank * 512;
    const int epi_r = lane >> 2, epi_c = (lane & 3) * 2;

    for (int s = 0; s < 2; s++)
        for (int kb = 0; kb < 8; kb++)
            load_tile(sV + (uint32_t)(s * 8 + kb) * 8192u,
                      Vs + (size_t)(cid * 64) * 2048 + s * 1024 + kbase + kb * 64,
                      64, 2048);

    float bias[8];
#pragma unroll
    for (int j = 0; j < 8; j++) {
        int n = col0 + j;
        int orig = ((n & 3) << 10) + (n >> 2);
        bias[j] = __ldg(b1 + orig) + __ldg(b2 + orig);
    }

    uint32_t gB_remote;
    asm("mapa.shared::cluster.u32 %0, %1, %2;"
        : "=r"(gB_remote) : "r"(sGB), "r"(rank ^ 1u));

    unsigned mygen;
    asm volatile("ld.relaxed.gpu.u32 %0, [%1];" : "=r"(mygen) : "l"(&g_arr[bx]));

    float2 c2 = make_float2(0.f, 0.f), h2 = make_float2(0.f, 0.f);
    __stcg(reinterpret_cast<unsigned*>(g_hs + (size_t)HB + b * 2048 + u0g), 0u);
    __stcg(reinterpret_cast<unsigned*>(g_hs + (size_t)HB + b * 2048 + 1024 + u0g), 0u);

    // prefetch step-0 pre slice before the first barrier
    const float* prow0 = pre + (size_t)b * NG + col0;
    float4 p0 = __ldg(reinterpret_cast<const float4*>(prow0));
    float4 p1 = __ldg(reinterpret_cast<const float4*>(prow0 + 4));

    grid_barrier(mygen);

    const bool own_half = (ni == (int)rank);

    for (int t = 0; t < SEQ; t++) {
        const bf16* hsrc = g_hs + (size_t)((t + 1) & 1) * HB + kbase;

        stage_A(sA, hsrc);
        asm volatile("cp.async.commit_group;");
        stage_A(sA + 16384u, hsrc + 64);
        asm volatile("cp.async.commit_group;");

        float acc[4][4];
#pragma unroll
        for (int f = 0; f < 4; f++)
#pragma unroll
            for (int j = 0; j < 4; j++) acc[f][j] = 0.f;

#pragma unroll 1
        for (int kb = 0; kb < 8; kb++) {
            if (kb == 7) asm volatile("cp.async.wait_group 0;");
            else         asm volatile("cp.async.wait_group 1;");
            __syncthreads();
            if (kb + 2 < 8) {
                stage_A(sA + (uint32_t)((kb + 2) % 3) * 16384u, hsrc + (kb + 2) * 64);
                asm volatile("cp.async.commit_group;");
            }
            const uint32_t ahB = sA + (uint32_t)(kb % 3) * 16384u;
            const uint32_t alB = ahB + 8192u;
            const uint32_t vhB = sV + (uint32_t)kb * 8192u;
            const uint32_t vlB = sV + (uint32_t)(8 + kb) * 8192u;
#pragma unroll
            for (int kst = 0; kst < 4; kst++) {
                const int k0 = kst * 16;
                uint32_t ah[4], al[4];
                ldsm4(ah, a_addr(ahB, lane, mi * 16, k0));
                ldsm4(al, a_addr(alB, lane, mi * 16, k0));
#pragma unroll
                for (int np = 0; np < 2; np++) {
                    const int nt = ni * 32 + np * 16;
                    uint32_t bh[4], bl[4];
                    ldsm4(bh, b_addr(vhB, lane, nt, k0));
                    ldsm4(bl, b_addr(vlB, lane, nt, k0));
                    mma16816(acc[np * 2],     ah, bh[0], bh[1]);
                    mma16816(acc[np * 2 + 1], ah, bh[2], bh[3]);
                    mma16816(acc[np * 2],     al, bh[0], bh[1]);
                    mma16816(acc[np * 2 + 1], al, bh[2], bh[3]);
                    mma16816(acc[np * 2],     ah, bl[0], bl[1]);
                    mma16816(acc[np * 2 + 1], ah, bl[2], bl[3]);
                }
            }
        }

        // epilogue: own-half cols -> local gA; partner-half cols -> remote gB
        {
            const int row = mi * 16 + epi_r;
#pragma unroll
            for (int np = 0; np < 2; np++) {
#pragma unroll
                for (int g = 0; g < 2; g++) {
                    const int colh = np * 16 + g * 8 + epi_c;
                    const float* f = acc[np * 2 + g];
                    const uint32_t off0 = (uint32_t)(row * GP + colh) * 4u;
                    const uint32_t off1 = (uint32_t)((row + 8) * GP + colh) * 4u;
                    if (own_half) {
                        asm volatile("st.shared.v2.f32 [%0], {%1,%2};"
                            :: "r"(sGA + off0), "f"(f[0]), "f"(f[1]));
                        asm volatile("st.shared.v2.f32 [%0], {%1,%2};"
                            :: "r"(sGA + off1), "f"(f[2]), "f"(f[3]));
                    } else {
                        asm volatile("st.shared::cluster.v2.f32 [%0], {%1,%2};"
                            :: "r"(gB_remote + off0), "f"(f[0]), "f"(f[1]) : "memory");
                        asm volatile("st.shared::cluster.v2.f32 [%0], {%1,%2};"
                            :: "r"(gB_remote + off1), "f"(f[2]), "f"(f[3]) : "memory");
                    }
                }
            }
        }
        asm volatile("barrier.cluster.arrive.aligned;" ::: "memory");
        asm volatile("barrier.cluster.wait.aligned;" ::: "memory");

        // pointwise: gates = own partial + partner partial + pre + bias
        float4 a0, a1, q0, q1;
        asm volatile("ld.shared.v4.f32 {%0,%1,%2,%3}, [%4];"
            : "=f"(a0.x), "=f"(a0.y), "=f"(a0.z), "=f"(a0.w)
            : "r"(sGA + (uint32_t)(b * GP + 4 * ul) * 4u));
        asm volatile("ld.shared.v4.f32 {%0,%1,%2,%3}, [%4];"
            : "=f"(a1.x), "=f"(a1.y), "=f"(a1.z), "=f"(a1.w)
            : "r"(sGA + (uint32_t)(b * GP + 4 * ul + 4) * 4u));
        asm volatile("ld.shared.v4.f32 {%0,%1,%2,%3}, [%4];"
            : "=f"(q0.x), "=f"(q0.y), "=f"(q0.z), "=f"(q0.w)
            : "r"(sGB + (uint32_t)(b * GP + 4 * ul) * 4u));
        asm volatile("ld.shared.v4.f32 {%0,%1,%2,%3}, [%4];"
            : "=f"(q1.x), "=f"(q1.y), "=f"(q1.z), "=f"(q1.w)
            : "r"(sGB + (uint32_t)(b * GP + 4 * ul + 4) * 4u));
        {
            float iv = sigmoid_acc(a0.x + q0.x + p0.x + bias[0]);
            float fv = sigmoid_acc(a0.y + q0.y + p0.y + bias[1]);
            float gv = tanh_acc   (a0.z + q0.z + p0.z + bias[2]);
            float ov = sigmoid_acc(a0.w + q0.w + p0.w + bias[3]);
            c2.x = fv * c2.x + iv * gv;
            h2.x = ov * tanh_acc(c2.x);
        }
        {
            float iv = sigmoid_acc(a1.x + q1.x + p1.x + bias[4]);
            float fv = sigmoid_acc(a1.y + q1.y + p1.y + bias[5]);
            float gv = tanh_acc   (a1.z + q1.z + p1.z + bias[6]);
            float ov = sigmoid_acc(a1.w + q1.w + p1.w + bias[7]);
            c2.y = fv * c2.y + iv * gv;
            h2.y = ov * tanh_acc(c2.y);
        }

        bf16 xh, xl, yh, yl;
        split2(h2.x, xh, xl);
        split2(h2.y, yh, yl);
        __nv_bfloat162 vhi = __halves2bfloat162(xh, yh);
        __nv_bfloat162 vlo = __halves2bfloat162(xl, yl);
        unsigned uhi = *reinterpret_cast<unsigned*>(&vhi);
        unsigned ulo = *reinterpret_cast<unsigned*>(&vlo);
        bf16* wdst = g_hs + (size_t)(t & 1) * HB + b * 2048;
        __stcg(reinterpret_cast<unsigned*>(wdst + u0g), uhi);
        __stcg(reinterpret_cast<unsigned*>(wdst + 1024 + u0g), ulo);
        if (outbuf)
            *reinterpret_cast<float2*>(outbuf + ((size_t)t * BATCH + b) * HS + u0g) = h2;
        if (xsplit) {
            bf16* xr = xsplit + ((size_t)t * BATCH + b) * 2048;
            *reinterpret_cast<unsigned*>(xr + u0g) = uhi;
            *reinterpret_cast<unsigned*>(xr + 1024 + u0g) = ulo;
        }

        // prefetch NEXT step's pre slice before the barrier (static data)
        if (t + 1 < SEQ) {
            const float* prow = pre + ((size_t)(t + 1) * BATCH + b) * NG + col0;
            p0 = __ldg(reinterpret_cast<const float4*>(prow));
            p1 = __ldg(reinterpret_cast<const float4*>(prow + 4));
        }

        grid_barrier(mygen);
    }

    *reinterpret_cast<float2*>(dh + b * HS + u0g) = h2;
    *reinterpret_cast<float2*>(dc + b * HS + u0g) = c2;
}

// =================================================================================
extern "C" void kernel_launch(void* const* d_in, const int* in_sizes, int n_in,
                              void* d_out, int out_size)
{
    const float* x   = (const float*)d_in[0];
    const float* U0  = (const float*)d_in[1];
    const float* V0  = (const float*)d_in[2];
    const float* bi0 = (const float*)d_in[3];
    const float* bh0 = (const float*)d_in[4];
    const float* U1  = (const float*)d_in[5];
    const float* V1  = (const float*)d_in[6];
    const float* bi1 = (const float*)d_in[7];
    const float* bh1 = (const float*)d_in[8];
    float* out = (float*)d_out;

    cudaFuncSetAttribute(k_inproj_t, cudaFuncAttributeMaxDynamicSharedMemorySize, SMEM_INPROJ);
    cudaFuncSetAttribute(k_layer_c,  cudaFuncAttributeMaxDynamicSharedMemorySize, SMEM_LAYER);

    float *pre = nullptr;
    bf16 *xs = nullptr, *us0 = nullptr, *vs0 = nullptr, *us1 = nullptr, *vs1 = nullptr;
    cudaGetSymbolAddress((void**)&pre, g_pre);
    cudaGetSymbolAddress((void**)&xs,  g_xs);
    cudaGetSymbolAddress((void**)&us0, g_Us0);
    cudaGetSymbolAddress((void**)&vs0, g_Vs0);
    cudaGetSymbolAddress((void**)&us1, g_Us1);
    cudaGetSymbolAddress((void**)&vs1, g_Vs1);

    const size_t O_OUT = (size_t)SEQ * BATCH * HS;
    const size_t BH    = (size_t)BATCH * HS;

    k_split_x<<<(MROWS * HS) / 256, 256>>>(x);
    {
        dim3 gsw((NG * HS) / 256, 4);
        k_split_w4<<<gsw, 256>>>(U0, V0, U1, V1, us0, vs0, us1, vs1);
    }

    const dim3 gIn(NG / 128, MROWS / 128);   // (32, 256)

    // layer 0 (h splits feed layer-1 inproj via g_xs)
    k_inproj_t<<<gIn, 256, SMEM_INPROJ>>>(xs, us0, pre);
    k_layer_c<<<NB_PERS, 256, SMEM_LAYER>>>(vs0, pre, bi0, bh0, nullptr, xs,
                                            out + O_OUT,            // h_f[0]
                                            out + O_OUT + 2 * BH);  // c_f[0]

    // layer 1
    k_inproj_t<<<gIn, 256, SMEM_INPROJ>>>(xs, us1, pre);
    k_layer_c<<<NB_PERS, 256, SMEM_LAYER>>>(vs1, pre, bi1, bh1, out, nullptr,
                                            out + O_OUT + BH,       // h_f[1]
                                            out + O_OUT + 3 * BH);  // c_f[1]
}

// round 15
// speedup vs baseline: 1.2914x; 1.2914x over previous
#include <cuda_runtime.h>
#include <cuda_bf16.h>
#include <cstdint>
#include <cstddef>

#define SEQ   512
#define BATCH 64
#define HS    1024
#define NG    4096
#define MROWS (SEQ*BATCH)     // 32768
#define NB_PERS 128
#define GP 36                 // padded gate-smem row stride (floats)
#define HB (BATCH*2*HS)       // one h buffer (hi|lo), elements
#define NCHUNK 32             // inproj k-chunks of 32
#define SMEM_INPROJ (3*32768 + 1024)
// layer: V 131072 | A 3x16384 | gA 9216 | gB 9216 | align 1024
#define SMEM_LAYER (1024 + 131072 + 49152 + 9216 + 9216)

typedef unsigned long long u64;
typedef __nv_bfloat16 bf16;

// ---------------- static device scratch ----------------
__device__ float g_pre[(size_t)MROWS * NG];          // gate pre-activations (permuted cols)
__device__ bf16  g_xs[(size_t)MROWS * 2 * HS];       // input splits (hi|lo); layer0 h splits
__device__ bf16  g_hs[2 * HB];                       // double-buffered h splits
__device__ bf16  g_Us0[(size_t)NG * 2 * HS];         // permuted weight splits
__device__ bf16  g_Vs0[(size_t)NG * 2 * HS];
__device__ bf16  g_Us1[(size_t)NG * 2 * HS];
__device__ bf16  g_Vs1[(size_t)NG * 2 * HS];

// ---------------- grid barrier (R13 atomic version — measured best) ----------------
__device__ unsigned g_cnt = 0;
__device__ unsigned g_gen = 0;

__device__ __forceinline__ void grid_barrier(unsigned& mygen) {
    __syncthreads();
    if (threadIdx.x == 0) {
        unsigned old;
        asm volatile("atom.add.acq_rel.gpu.u32 %0, [%1], 1;"
                     : "=r"(old) : "l"(&g_cnt) : "memory");
        if (old == (unsigned)(NB_PERS - 1)) {
            asm volatile("st.relaxed.gpu.u32 [%0], 0;" :: "l"(&g_cnt) : "memory");
            asm volatile("red.release.gpu.add.u32 [%0], 1;" :: "l"(&g_gen) : "memory");
        } else {
            unsigned cur;
            do {
                __nanosleep(20);
                asm volatile("ld.acquire.gpu.u32 %0, [%1];"
                             : "=r"(cur) : "l"(&g_gen) : "memory");
            } while (cur == mygen);
        }
    }
    mygen += 1;
    __syncthreads();
}

// ---------------- mma.sync building blocks (validated R4-R14) ----------------
__device__ __forceinline__ uint32_t smem_u32(const void* p) {
    uint32_t a;
    asm("{ .reg .u64 t; cvta.to.shared.u64 t, %1; cvt.u32.u64 %0, t; }" : "=r"(a) : "l"(p));
    return a;
}
__device__ __forceinline__ void ldsm4(uint32_t* f, uint32_t addr) {
    asm volatile("ldmatrix.sync.aligned.m8n8.x4.shared.b16 {%0,%1,%2,%3}, [%4];"
        : "=r"(f[0]), "=r"(f[1]), "=r"(f[2]), "=r"(f[3]) : "r"(addr));
}
__device__ __forceinline__ void mma16816(float* d, const uint32_t* a, uint32_t b0, uint32_t b1) {
    asm volatile("mma.sync.aligned.m16n8k16.row.col.f32.bf16.bf16.f32 "
        "{%0,%1,%2,%3}, {%4,%5,%6,%7}, {%8,%9}, {%0,%1,%2,%3};"
        : "+f"(d[0]), "+f"(d[1]), "+f"(d[2]), "+f"(d[3])
        : "r"(a[0]), "r"(a[1]), "r"(a[2]), "r"(a[3]), "r"(b0), "r"(b1));
}
__device__ __forceinline__ uint32_t swz(uint32_t r, uint32_t c16) {
    return r * 128u + ((c16 ^ (r & 7u)) << 4);
}
__device__ __forceinline__ uint32_t a_addr(uint32_t base, int lane, int m0, int k0) {
    int sel = lane >> 3;
    uint32_t row = (uint32_t)(m0 + (lane & 7) + ((sel & 1) << 3));
    uint32_t c16 = (uint32_t)((k0 >> 3) + (sel >> 1));
    return base + swz(row, c16);
}
__device__ __forceinline__ uint32_t b_addr(uint32_t base, int lane, int n0, int k0) {
    int sel = lane >> 3;
    uint32_t row = (uint32_t)(n0 + (lane & 7) + ((sel >> 1) << 3));
    uint32_t c16 = (uint32_t)((k0 >> 3) + (sel & 1));
    return base + swz(row, c16);
}
__device__ __forceinline__ void cp16(uint32_t dst, const void* src) {
    asm volatile("cp.async.cg.shared.global [%0], [%1], 16;" :: "r"(dst), "l"(src));
}

// sync-path tile load into swizzled smem ([rows x 64] bf16, row stride ld)
__device__ __forceinline__ void load_tile(uint32_t sdst, const bf16* __restrict__ src,
                                          int rows, int ld) {
    const int chunks = rows * 8;
    for (int i = threadIdx.x; i < chunks; i += 256) {
        int r = i >> 3, c = i & 7;
        const uint4* p = reinterpret_cast<const uint4*>(src + (size_t)r * ld + c * 8);
        uint4 v = __ldg(p);
        asm volatile("st.shared.v4.b32 [%0], {%1,%2,%3,%4};"
                     :: "r"(sdst + swz((uint32_t)r, (uint32_t)c)),
                        "r"(v.x), "r"(v.y), "r"(v.z), "r"(v.w));
    }
}
// async stage of a combined [128 x 64] tile: cols 0-31 = hi k-chunk, 32-63 = lo.
__device__ __forceinline__ void stage_tile_hilo(uint32_t sdst, const bf16* __restrict__ src) {
    const int tid = threadIdx.x;
#pragma unroll
    for (int q = 0; q < 4; q++) {
        int i = tid + q * 256;
        int r = i >> 3, c = i & 7;
        const bf16* s = src + (size_t)r * 2048 + (c < 4 ? c * 8 : 1024 + (c - 4) * 8);
        cp16(sdst + swz((uint32_t)r, (uint32_t)c), s);
    }
}
// async stage: A pair (64 rows x 64 cols, hi tile + lo tile of 8KB each)
__device__ __forceinline__ void stage_A(uint32_t sdst, const bf16* __restrict__ src) {
    const int tid = threadIdx.x;
#pragma unroll
    for (int s = 0; s < 2; s++) {
#pragma unroll
        for (int q = 0; q < 2; q++) {
            int i = tid + q * 256;
            int r = i >> 3, c = i & 7;
            cp16(sdst + (uint32_t)s * 8192u + swz((uint32_t)r, (uint32_t)c),
                 src + s * 1024 + (size_t)r * 2048 + c * 8);
        }
    }
}

// ---------------- activations ----------------
__device__ __forceinline__ float sigmoid_acc(float x) {
    return 1.0f / (1.0f + __expf(-x));
}
__device__ __forceinline__ float tanh_acc(float x) {
    float e = __expf(-2.0f * fabsf(x));
    float t = (1.0f - e) / (1.0f + e);
    return copysignf(t, x);
}
__device__ __forceinline__ void split2(float v, bf16& hi, bf16& lo) {
    hi = __float2bfloat16(v);
    lo = __float2bfloat16(v - __bfloat162float(hi));
}

// =================================================================================
// split kernels. Weight rows gate-permuted: orig row r = g*1024+u -> 4u+g.
// =================================================================================
__global__ __launch_bounds__(256) void k_split_x(const float* __restrict__ x) {
    size_t i = (size_t)blockIdx.x * 256 + threadIdx.x;
    size_t m = i >> 10, k = i & 1023;
    bf16 hi, lo; split2(x[i], hi, lo);
    g_xs[m * 2048 + k]        = hi;
    g_xs[m * 2048 + 1024 + k] = lo;
}
__global__ __launch_bounds__(256) void k_split_w4(
    const float* __restrict__ W0, const float* __restrict__ W1,
    const float* __restrict__ W2, const float* __restrict__ W3,
    bf16* __restrict__ d0, bf16* __restrict__ d1,
    bf16* __restrict__ d2, bf16* __restrict__ d3)
{
    const float* W; bf16* dst;
    switch (blockIdx.y) {
        case 0:  W = W0; dst = d0; break;
        case 1:  W = W1; dst = d1; break;
        case 2:  W = W2; dst = d2; break;
        default: W = W3; dst = d3; break;
    }
    size_t i = (size_t)blockIdx.x * 256 + threadIdx.x;
    size_t n = i >> 10, k = i & 1023;
    size_t gidx = n >> 10, u = n & 1023;
    size_t np = u * 4 + gidx;
    bf16 hi, lo; split2(W[i], hi, lo);
    dst[np * 2048 + k]        = hi;
    dst[np * 2048 + 1024 + k] = lo;
}

// =================================================================================
// Input projection — unchanged R7/R12 config (measured 74.9% tensor = near ceiling).
// =================================================================================
__global__ __launch_bounds__(256, 2) void k_inproj_t(
    const bf16* __restrict__ A, const bf16* __restrict__ W,
    float* __restrict__ C)
{
    extern __shared__ char dsm[];
    const uint32_t sbase = (smem_u32(dsm) + 1023u) & ~1023u;
    const int tid = threadIdx.x, wid = tid >> 5, lane = tid & 31;
    const int m0 = blockIdx.y * 128, n0 = blockIdx.x * 128;
    const int mi = wid & 3, ni = wid >> 2;

    const bf16* Arow = A + (size_t)m0 * 2048;
    const bf16* Wrow = W + (size_t)n0 * 2048;

    auto issue_stage = [&](int kb) {
        const uint32_t st = sbase + (uint32_t)(kb % 3) * 32768u;
        stage_tile_hilo(st,          Arow + kb * 32);
        stage_tile_hilo(st + 16384u, Wrow + kb * 32);
        asm volatile("cp.async.commit_group;");
    };

    float acc[2][8][4];
#pragma unroll
    for (int a = 0; a < 2; a++)
#pragma unroll
        for (int b = 0; b < 8; b++)
#pragma unroll
            for (int cpos = 0; cpos < 4; cpos++) acc[a][b][cpos] = 0.f;

    issue_stage(0);
    issue_stage(1);

#pragma unroll 1
    for (int kb = 0; kb < NCHUNK; kb++) {
        if (kb == NCHUNK - 1) asm volatile("cp.async.wait_group 0;");
        else                  asm volatile("cp.async.wait_group 1;");
        __syncthreads();
        if (kb + 2 < NCHUNK) issue_stage(kb + 2);

        const uint32_t st = sbase + (uint32_t)(kb % 3) * 32768u;
        const uint32_t sA = st, sB = st + 16384u;
#pragma unroll
        for (int ks = 0; ks < 2; ks++) {
            const int k0 = ks * 16;
            uint32_t ah[2][4], al[2][4];
#pragma unroll
            for (int mf = 0; mf < 2; mf++) {
                ldsm4(ah[mf], a_addr(sA, lane, mi * 32 + mf * 16, k0));
                ldsm4(al[mf], a_addr(sA, lane, mi * 32 + mf * 16, k0 + 32));
            }
#pragma unroll
            for (int np = 0; np < 4; np++) {
                const int nt = ni * 64 + np * 16;
                uint32_t bh[4], bl[4];
                ldsm4(bh, b_addr(sB, lane, nt, k0));
#pragma unroll
                for (int mf = 0; mf < 2; mf++) {
                    mma16816(acc[mf][np * 2],     ah[mf], bh[0], bh[1]);
                    mma16816(acc[mf][np * 2 + 1], ah[mf], bh[2], bh[3]);
                    mma16816(acc[mf][np * 2],     al[mf], bh[0], bh[1]);
                    mma16816(acc[mf][np * 2 + 1], al[mf], bh[2], bh[3]);
                }
                ldsm4(bl, b_addr(sB, lane, nt, k0 + 32));
#pragma unroll
                for (int mf = 0; mf < 2; mf++) {
                    mma16816(acc[mf][np * 2],     ah[mf], bl[0], bl[1]);
                    mma16816(acc[mf][np * 2 + 1], ah[mf], bl[2], bl[3]);
                }
            }
        }
    }

    const int r = lane >> 2, cq = (lane & 3) * 2;
#pragma unroll
    for (int mf = 0; mf < 2; mf++) {
#pragma unroll
        for (int nf = 0; nf < 8; nf++) {
            const int ncol = n0 + ni * 64 + nf * 8 + cq;
            const int row0 = m0 + mi * 32 + mf * 16 + r;
            *reinterpret_cast<float2*>(C + (size_t)row0 * NG + ncol) =
                make_float2(acc[mf][nf][0], acc[mf][nf][1]);
            *reinterpret_cast<float2*>(C + (size_t)(row0 + 8) * NG + ncol) =
                make_float2(acc[mf][nf][2], acc[mf][nf][3]);
        }
    }
}

// =================================================================================
// Persistent LSTM layer, CLUSTERED K-SPLIT (R13 winner), with:
//  - R13 atomic grid barrier (reverted from R14's flag array)
//  - pre[t+1] register prefetch
//  - HMMA terms reordered: per kst, all 4 B-frags hoisted, mma grouped by term
//    (hh,lh,hl) x 4 accumulators -> dep distance 4 (was 2). Per-acc summation
//    order unchanged -> bitwise-identical results.
// =================================================================================
__global__ __launch_bounds__(256) __cluster_dims__(2, 1, 1)
void k_layer_c(
    const bf16* __restrict__ Vs, const float* __restrict__ pre,
    const float* __restrict__ b1, const float* __restrict__ b2,
    float* __restrict__ outbuf, bf16* __restrict__ xsplit,
    float* __restrict__ dh, float* __restrict__ dc)
{
    extern __shared__ char dsm[];
    const uint32_t sbase = (smem_u32(dsm) + 1023u) & ~1023u;
    const uint32_t sV  = sbase;               // 16 tiles x 8192 (hi 0..7, lo 8..15)
    const uint32_t sA  = sbase + 131072u;     // 3 stages x 16384
    const uint32_t sGA = sbase + 180224u;     // own partial   [64][GP] fp32
    const uint32_t sGB = sbase + 189440u;     // partner partial [64][GP] fp32
    const int tid = threadIdx.x, wid = tid >> 5, lane = tid & 31;
    const int bx = blockIdx.x;
    const int cid = bx >> 1;
    uint32_t rank;
    asm("mov.u32 %0, %%cluster_ctarank;" : "=r"(rank));
    const int mi = wid & 3, ni = wid >> 2;
    const int b  = tid >> 2;
    const int ul = (tid & 3) * 2;
    const int u0g  = cid * 16 + (int)rank * 8 + ul;
    const int col0 = 4 * u0g;
    const int kbase = (int)rank * 512;
    const int epi_r = lane >> 2, epi_c = (lane & 3) * 2;

    for (int s = 0; s < 2; s++)
        for (int kb = 0; kb < 8; kb++)
            load_tile(sV + (uint32_t)(s * 8 + kb) * 8192u,
                      Vs + (size_t)(cid * 64) * 2048 + s * 1024 + kbase + kb * 64,
                      64, 2048);

    float bias[8];
#pragma unroll
    for (int j = 0; j < 8; j++) {
        int n = col0 + j;
        int orig = ((n & 3) << 10) + (n >> 2);
        bias[j] = __ldg(b1 + orig) + __ldg(b2 + orig);
    }

    uint32_t gB_remote;
    asm("mapa.shared::cluster.u32 %0, %1, %2;"
        : "=r"(gB_remote) : "r"(sGB), "r"(rank ^ 1u));

    unsigned mygen;
    asm volatile("ld.relaxed.gpu.u32 %0, [%1];" : "=r"(mygen) : "l"(&g_gen));

    float2 c2 = make_float2(0.f, 0.f), h2 = make_float2(0.f, 0.f);
    __stcg(reinterpret_cast<unsigned*>(g_hs + (size_t)HB + b * 2048 + u0g), 0u);
    __stcg(reinterpret_cast<unsigned*>(g_hs + (size_t)HB + b * 2048 + 1024 + u0g), 0u);

    // prefetch step-0 pre slice before the first barrier
    const float* prow0 = pre + (size_t)b * NG + col0;
    float4 p0 = __ldg(reinterpret_cast<const float4*>(prow0));
    float4 p1 = __ldg(reinterpret_cast<const float4*>(prow0 + 4));

    grid_barrier(mygen);

    const bool own_half = (ni == (int)rank);

    for (int t = 0; t < SEQ; t++) {
        const bf16* hsrc = g_hs + (size_t)((t + 1) & 1) * HB + kbase;

        stage_A(sA, hsrc);
        asm volatile("cp.async.commit_group;");
        stage_A(sA + 16384u, hsrc + 64);
        asm volatile("cp.async.commit_group;");

        float acc[4][4];
#pragma unroll
        for (int f = 0; f < 4; f++)
#pragma unroll
            for (int j = 0; j < 4; j++) acc[f][j] = 0.f;

#pragma unroll 1
        for (int kb = 0; kb < 8; kb++) {
            if (kb == 7) asm volatile("cp.async.wait_group 0;");
            else         asm volatile("cp.async.wait_group 1;");
            __syncthreads();
            if (kb + 2 < 8) {
                stage_A(sA + (uint32_t)((kb + 2) % 3) * 16384u, hsrc + (kb + 2) * 64);
                asm volatile("cp.async.commit_group;");
            }
            const uint32_t ahB = sA + (uint32_t)(kb % 3) * 16384u;
            const uint32_t alB = ahB + 8192u;
            const uint32_t vhB = sV + (uint32_t)kb * 8192u;
            const uint32_t vlB = sV + (uint32_t)(8 + kb) * 8192u;
#pragma unroll
            for (int kst = 0; kst < 4; kst++) {
                const int k0 = kst * 16;
                uint32_t ah[4], al[4], bh0[4], bl0[4], bh1[4], bl1[4];
                ldsm4(ah, a_addr(ahB, lane, mi * 16, k0));
                ldsm4(al, a_addr(alB, lane, mi * 16, k0));
                ldsm4(bh0, b_addr(vhB, lane, ni * 32, k0));
                ldsm4(bh1, b_addr(vhB, lane, ni * 32 + 16, k0));
                ldsm4(bl0, b_addr(vlB, lane, ni * 32, k0));
                ldsm4(bl1, b_addr(vlB, lane, ni * 32 + 16, k0));
                // term hh: all 4 accumulators (dep distance 4)
                mma16816(acc[0], ah, bh0[0], bh0[1]);
                mma16816(acc[1], ah, bh0[2], bh0[3]);
                mma16816(acc[2], ah, bh1[0], bh1[1]);
                mma16816(acc[3], ah, bh1[2], bh1[3]);
                // term lh
                mma16816(acc[0], al, bh0[0], bh0[1]);
                mma16816(acc[1], al, bh0[2], bh0[3]);
                mma16816(acc[2], al, bh1[0], bh1[1]);
                mma16816(acc[3], al, bh1[2], bh1[3]);
                // term hl
                mma16816(acc[0], ah, bl0[0], bl0[1]);
                mma16816(acc[1], ah, bl0[2], bl0[3]);
                mma16816(acc[2], ah, bl1[0], bl1[1]);
                mma16816(acc[3], ah, bl1[2], bl1[3]);
            }
        }

        // epilogue: own-half cols -> local gA; partner-half cols -> remote gB
        {
            const int row = mi * 16 + epi_r;
#pragma unroll
            for (int np = 0; np < 2; np++) {
#pragma unroll
                for (int g = 0; g < 2; g++) {
                    const int colh = np * 16 + g * 8 + epi_c;
                    const float* f = acc[np * 2 + g];
                    const uint32_t off0 = (uint32_t)(row * GP + colh) * 4u;
                    const uint32_t off1 = (uint32_t)((row + 8) * GP + colh) * 4u;
                    if (own_half) {
                        asm volatile("st.shared.v2.f32 [%0], {%1,%2};"
                            :: "r"(sGA + off0), "f"(f[0]), "f"(f[1]));
                        asm volatile("st.shared.v2.f32 [%0], {%1,%2};"
                            :: "r"(sGA + off1), "f"(f[2]), "f"(f[3]));
                    } else {
                        asm volatile("st.shared::cluster.v2.f32 [%0], {%1,%2};"
                            :: "r"(gB_remote + off0), "f"(f[0]), "f"(f[1]) : "memory");
                        asm volatile("st.shared::cluster.v2.f32 [%0], {%1,%2};"
                            :: "r"(gB_remote + off1), "f"(f[2]), "f"(f[3]) : "memory");
                    }
                }
            }
        }
        asm volatile("barrier.cluster.arrive.aligned;" ::: "memory");
        asm volatile("barrier.cluster.wait.aligned;" ::: "memory");

        // pointwise: gates = own partial + partner partial + pre + bias
        float4 a0, a1, q0, q1;
        asm volatile("ld.shared.v4.f32 {%0,%1,%2,%3}, [%4];"
            : "=f"(a0.x), "=f"(a0.y), "=f"(a0.z), "=f"(a0.w)
            : "r"(sGA + (uint32_t)(b * GP + 4 * ul) * 4u));
        asm volatile("ld.shared.v4.f32 {%0,%1,%2,%3}, [%4];"
            : "=f"(a1.x), "=f"(a1.y), "=f"(a1.z), "=f"(a1.w)
            : "r"(sGA + (uint32_t)(b * GP + 4 * ul + 4) * 4u));
        asm volatile("ld.shared.v4.f32 {%0,%1,%2,%3}, [%4];"
            : "=f"(q0.x), "=f"(q0.y), "=f"(q0.z), "=f"(q0.w)
            : "r"(sGB + (uint32_t)(b * GP + 4 * ul) * 4u));
        asm volatile("ld.shared.v4.f32 {%0,%1,%2,%3}, [%4];"
            : "=f"(q1.x), "=f"(q1.y), "=f"(q1.z), "=f"(q1.w)
            : "r"(sGB + (uint32_t)(b * GP + 4 * ul + 4) * 4u));
        {
            float iv = sigmoid_acc(a0.x + q0.x + p0.x + bias[0]);
            float fv = sigmoid_acc(a0.y + q0.y + p0.y + bias[1]);
            float gv = tanh_acc   (a0.z + q0.z + p0.z + bias[2]);
            float ov = sigmoid_acc(a0.w + q0.w + p0.w + bias[3]);
            c2.x = fv * c2.x + iv * gv;
            h2.x = ov * tanh_acc(c2.x);
        }
        {
            float iv = sigmoid_acc(a1.x + q1.x + p1.x + bias[4]);
            float fv = sigmoid_acc(a1.y + q1.y + p1.y + bias[5]);
            float gv = tanh_acc   (a1.z + q1.z + p1.z + bias[6]);
            float ov = sigmoid_acc(a1.w + q1.w + p1.w + bias[7]);
            c2.y = fv * c2.y + iv * gv;
            h2.y = ov * tanh_acc(c2.y);
        }

        bf16 xh, xl, yh, yl;
        split2(h2.x, xh, xl);
        split2(h2.y, yh, yl);
        __nv_bfloat162 vhi = __halves2bfloat162(xh, yh);
        __nv_bfloat162 vlo = __halves2bfloat162(xl, yl);
        unsigned uhi = *reinterpret_cast<unsigned*>(&vhi);
        unsigned ulo = *reinterpret_cast<unsigned*>(&vlo);
        bf16* wdst = g_hs + (size_t)(t & 1) * HB + b * 2048;
        __stcg(reinterpret_cast<unsigned*>(wdst + u0g), uhi);
        __stcg(reinterpret_cast<unsigned*>(wdst + 1024 + u0g), ulo);
        if (outbuf)
            *reinterpret_cast<float2*>(outbuf + ((size_t)t * BATCH + b) * HS + u0g) = h2;
        if (xsplit) {
            bf16* xr = xsplit + ((size_t)t * BATCH + b) * 2048;
            *reinterpret_cast<unsigned*>(xr + u0g) = uhi;
            *reinterpret_cast<unsigned*>(xr + 1024 + u0g) = ulo;
        }

        // prefetch NEXT step's pre slice before the barrier (static data)
        if (t + 1 < SEQ) {
            const float* prow = pre + ((size_t)(t + 1) * BATCH + b) * NG + col0;
            p0 = __ldg(reinterpret_cast<const float4*>(prow));
            p1 = __ldg(reinterpret_cast<const float4*>(prow + 4));
        }

        grid_barrier(mygen);
    }

    *reinterpret_cast<float2*>(dh + b * HS + u0g) = h2;
    *reinterpret_cast<float2*>(dc + b * HS + u0g) = c2;
}

// =================================================================================
extern "C" void kernel_launch(void* const* d_in, const int* in_sizes, int n_in,
                              void* d_out, int out_size)
{
    const float* x   = (const float*)d_in[0];
    const float* U0  = (const float*)d_in[1];
    const float* V0  = (const float*)d_in[2];
    const float* bi0 = (const float*)d_in[3];
    const float* bh0 = (const float*)d_in[4];
    const float* U1  = (const float*)d_in[5];
    const float* V1  = (const float*)d_in[6];
    const float* bi1 = (const float*)d_in[7];
    const float* bh1 = (const float*)d_in[8];
    float* out = (float*)d_out;

    cudaFuncSetAttribute(k_inproj_t, cudaFuncAttributeMaxDynamicSharedMemorySize, SMEM_INPROJ);
    cudaFuncSetAttribute(k_layer_c,  cudaFuncAttributeMaxDynamicSharedMemorySize, SMEM_LAYER);

    float *pre = nullptr;
    bf16 *xs = nullptr, *us0 = nullptr, *vs0 = nullptr, *us1 = nullptr, *vs1 = nullptr;
    cudaGetSymbolAddress((void**)&pre, g_pre);
    cudaGetSymbolAddress((void**)&xs,  g_xs);
    cudaGetSymbolAddress((void**)&us0, g_Us0);
    cudaGetSymbolAddress((void**)&vs0, g_Vs0);
    cudaGetSymbolAddress((void**)&us1, g_Us1);
    cudaGetSymbolAddress((void**)&vs1, g_Vs1);

    const size_t O_OUT = (size_t)SEQ * BATCH * HS;
    const size_t BH    = (size_t)BATCH * HS;

    k_split_x<<<(MROWS * HS) / 256, 256>>>(x);
    {
        dim3 gsw((NG * HS) / 256, 4);
        k_split_w4<<<gsw, 256>>>(U0, V0, U1, V1, us0, vs0, us1, vs1);
    }

    const dim3 gIn(NG / 128, MROWS / 128);   // (32, 256)

    // layer 0 (h splits feed layer-1 inproj via g_xs)
    k_inproj_t<<<gIn, 256, SMEM_INPROJ>>>(xs, us0, pre);
    k_layer_c<<<NB_PERS, 256, SMEM_LAYER>>>(vs0, pre, bi0, bh0, nullptr, xs,
                                            out + O_OUT,            // h_f[0]
                                            out + O_OUT + 2 * BH);  // c_f[0]

    // layer 1
    k_inproj_t<<<gIn, 256, SMEM_INPROJ>>>(xs, us1, pre);
    k_layer_c<<<NB_PERS, 256, SMEM_LAYER>>>(vs1, pre, bi1, bh1, out, nullptr,
                                            out + O_OUT + BH,       // h_f[1]
                                            out + O_OUT + 3 * BH);  // c_f[1]
}